// round 12
// baseline (speedup 1.0000x reference)
#include <cuda_runtime.h>
#include <cstdint>

#define NSAMP 256
#define EMB   120
#define DIN   64
#define MODES 16
#define NPH   8

#define PIf 3.14159265358979323846f

typedef unsigned long long ull;

// Persistent scratch for V, stored TRANSPOSED: [n][c][m] (c=0..7, m=0..15)
__device__ float2 g_V[NSAMP * NPH * MODES];

__device__ __forceinline__ float2 cmul(float2 a, float2 b) {
    return make_float2(a.x * b.x - a.y * b.y, a.x * b.y + a.y * b.x);
}

// Packed dual-FMA / dual-ADD on native 64-bit operands (single issue slot)
__device__ __forceinline__ ull ffma2p(ull a, ull b, ull c) {
    ull d;
    asm("fma.rn.f32x2 %0, %1, %2, %3;" : "=l"(d) : "l"(a), "l"(b), "l"(c));
    return d;
}
__device__ __forceinline__ ull fadd2p(ull a, ull b) {
    ull d;
    asm("add.rn.f32x2 %0, %1, %2;" : "=l"(d) : "l"(a), "l"(b));
    return d;
}
__device__ __forceinline__ ull pack2(float x, float y) {
    ull d; asm("mov.b64 %0, {%1, %2};" : "=l"(d) : "f"(x), "f"(y)); return d;
}
__device__ __forceinline__ float2 unpack2(ull a) {
    float2 f; asm("mov.b64 {%0, %1}, %2;" : "=f"(f.x), "=f"(f.y) : "l"(a)); return f;
}

// ---------------------------------------------------------------------------
// Kernel A: x_emb = sigmoid(x @ W^T + b); build V[n] (16x8 complex) per sample.
// V propagation parallelized over 64 threads: lane layout c-major so the
// odd-layer row exchange is shfl(+-1); no syncs inside the layer loop.
// ---------------------------------------------------------------------------
__global__ void __launch_bounds__(128) emb_v_kernel(
    const float* __restrict__ x,
    const float* __restrict__ W,
    const float* __restrict__ b,
    float* __restrict__ out_emb)
{
    const int n = blockIdx.x;
    const int t = threadIdx.x;

    __shared__ float xs[DIN];
    __shared__ float semb[EMB];
    __shared__ float4 trig[60];

    if (t < DIN) xs[t] = x[n * DIN + t];
    __syncthreads();

    if (t < EMB) {
        float acc = b[t];
        const float* wr = W + t * DIN;
        #pragma unroll
        for (int j = 0; j < DIN; j++) acc += xs[j] * wr[j];
        float s = 1.0f / (1.0f + expf(-acc));
        semb[t] = s;
        out_emb[n * EMB + t] = s;
    }
    __syncthreads();

    if (t < 60) {
        float th = semb[2 * t]     * (0.5f * PIf);
        float ph = semb[2 * t + 1] * (2.0f * PIf);
        float st_, ct_, sp_, cp_;
        sincosf(th, &st_, &ct_);
        sincosf(ph, &sp_, &cp_);
        trig[t] = make_float4(ct_, st_, cp_, sp_);
    }
    __syncthreads();

    // 64 threads: tid = c*8 + p ; thread holds rows 2p, 2p+1 of column c.
    if (t < 64) {
        const int p = t & 7;
        const int lane = t & 31;
        float2 t0 = make_float2((2 * p     == (t >> 3)) ? 1.0f : 0.0f, 0.0f);
        float2 t1 = make_float2((2 * p + 1 == (t >> 3)) ? 1.0f : 0.0f, 0.0f);
        // column c = t>>3; initial V = I[:, :8], so row m, col c: delta(m==c)

        const int NB[8]  = {8, 7, 8, 7, 8, 7, 8, 7};
        const int NBF[8] = {0, 8, 15, 23, 30, 38, 45, 53};

        #pragma unroll
        for (int d = 0; d < 8; d++) {
            if ((d & 1) == 0) {
                // even layer: rows (2p, 2p+1)
                float4 tg = trig[NBF[d] + p];
                float2 epct = make_float2(tg.z * tg.x, tg.w * tg.x);
                float2 epst = make_float2(tg.z * tg.y, tg.w * tg.y);
                float2 n0 = cmul(epct, t0);
                n0.x -= tg.y * t1.x;  n0.y -= tg.y * t1.y;
                float2 n1 = cmul(epst, t0);
                n1.x += tg.x * t1.x;  n1.y += tg.x * t1.y;
                t0 = n0;  t1 = n1;
            } else {
                // odd layer: pairs (2p+1, 2p+2) for p<7.
                // vlow = my t1; vhigh = neighbor (p+1)'s t0 via shfl down.
                float2 vlow = t1;
                float2 vhigh;
                vhigh.x = __shfl_sync(0xFFFFFFFFu, t0.x, lane + 1, 32);
                vhigh.y = __shfl_sync(0xFFFFFFFFu, t0.y, lane + 1, 32);
                float2 nlow = vlow, nhigh = vhigh;
                if (p < 7) {
                    float4 tg = trig[NBF[d] + p];
                    float2 epct = make_float2(tg.z * tg.x, tg.w * tg.x);
                    float2 epst = make_float2(tg.z * tg.y, tg.w * tg.y);
                    nlow = cmul(epct, vlow);
                    nlow.x -= tg.y * vhigh.x;  nlow.y -= tg.y * vhigh.y;
                    nhigh = cmul(epst, vlow);
                    nhigh.x += tg.x * vhigh.x; nhigh.y += tg.x * vhigh.y;
                    t1 = nlow;
                }
                // row 2p comes back from neighbor (p-1)'s nhigh
                float2 back;
                back.x = __shfl_sync(0xFFFFFFFFu, nhigh.x, lane - 1, 32);
                back.y = __shfl_sync(0xFFFFFFFFu, nhigh.y, lane - 1, 32);
                if (p > 0) t0 = back;
            }
        }

        const int c = t >> 3;
        g_V[n * (NPH * MODES) + c * MODES + 2 * p]     = t0;
        g_V[n * (NPH * MODES) + c * MODES + 2 * p + 1] = t1;
    }
}

// ---------------------------------------------------------------------------
// Kernel B (triangular, GLYNN): one warp per pair (a,b), bg >= qa tiles.
// perm(G) = 2^{1-8} * sum over 128 delta assignments (Gray coded) of
//   sign * prod_j S_j,  S_j = sum_i delta_i G[i][j].
// Lane t handles Gray indices 4t..4t+3.
// ---------------------------------------------------------------------------
#define VROW 18   // padded row stride (float2 units)

__global__ void __launch_bounds__(256) pair_kernel_tri(float* __restrict__ Kout)
{
    const int tid  = threadIdx.x;
    const int w    = tid >> 5;
    const int lane = tid & 31;

    // Decode macro-tile: t in [0,528) -> (bg, qa) with qa <= bg
    const int tIdx = blockIdx.x >> 3;
    const int ai   = blockIdx.x & 7;
    int bg = (int)((sqrtf(8.0f * (float)tIdx + 1.0f) - 1.0f) * 0.5f);
    if ((bg + 1) * (bg + 2) / 2 <= tIdx) bg++;
    if (bg * (bg + 1) / 2 > tIdx) bg--;
    const int qa   = tIdx - bg * (bg + 1) / 2;
    const int a    = qa * 8 + ai;
    const int bcol = bg * 8 + w;

    __shared__ alignas(16) float2 sVa[NPH * VROW];      // [i*18 + m]
    __shared__ alignas(16) float2 sVb[8][NPH * VROW];   // [w][j*18 + m]
    __shared__ alignas(16) ull    sAR[8][64];           // row-major: [w][i*8 + j]

    if (tid < NPH * MODES) {
        const int row = tid >> 4, m = tid & 15;
        sVa[row * VROW + m] = g_V[a * (NPH * MODES) + tid];
    }
    const bool active = (bcol > a);
    if (active) {
        #pragma unroll
        for (int r = 0; r < 4; r++) {
            const int idx = lane + r * 32;
            const int row = idx >> 4, m = idx & 15;
            sVb[w][row * VROW + m] = g_V[bcol * (NPH * MODES) + idx];
        }
    }
    __syncthreads();

    if (bcol < a) return;
    if (bcol == a) {
        if (lane == 0) Kout[a * NSAMP + a] = 1.0f;
        return;
    }

    // G[i][j] = sum_m conj(Va[m][i]) * Vb[m][j]; lane computes 2 entries.
    #pragma unroll
    for (int e = 0; e < 2; e++) {
        const int idx = lane + e * 32;
        const int i = idx >> 3, j = idx & 7;
        const float4* pa = (const float4*)&sVa[i * VROW];
        const float4* pb = (const float4*)&sVb[w][j * VROW];
        float2 acc = make_float2(0.0f, 0.0f);
        #pragma unroll
        for (int mm = 0; mm < 8; mm++) {
            float4 va2 = pa[mm];
            float4 vb2 = pb[mm];
            acc.x += va2.x * vb2.x + va2.y * vb2.y;
            acc.y += va2.x * vb2.y - va2.y * vb2.x;
            acc.x += va2.z * vb2.z + va2.w * vb2.w;
            acc.y += va2.z * vb2.w - va2.w * vb2.z;
        }
        sAR[w][idx] = pack2(acc.x, acc.y);   // row-major store: [i*8 + j]
    }
    __syncwarp();

    // Register-cache row 1 (delta bit 0: + in init, flips at k=1,3).
    ull rr1[8];
    {
        const ulonglong2* r1 = (const ulonglong2*)&sAR[w][8];
        #pragma unroll
        for (int q = 0; q < 4; q++) {
            ulonglong2 v = r1[q];
            rr1[2*q] = v.x; rr1[2*q+1] = v.y;
        }
    }

    // Gray state: g = gray(4*lane) over 7 bits (bit b <-> row b+1); bit0 = 0.
    unsigned g = ((4u * lane) ^ (2u * lane)) & 0x7Fu;

    // Init S = row0 + row1 + sum_{b=1..6} (1-2*bit_b) * row_{b+1}
    ull S[8];
    {
        const ulonglong2* r0 = (const ulonglong2*)&sAR[w][0];
        #pragma unroll
        for (int q = 0; q < 4; q++) {
            ulonglong2 v = r0[q];
            S[2*q]   = fadd2p(v.x, rr1[2*q]);
            S[2*q+1] = fadd2p(v.y, rr1[2*q+1]);
        }
    }
    #pragma unroll
    for (int b = 1; b < 7; b++) {
        const float cf = 1.0f - 2.0f * (float)((g >> b) & 1u);
        const ull mp = pack2(cf, cf);
        const ulonglong2* row = (const ulonglong2*)&sAR[w][(b + 1) * 8];
        #pragma unroll
        for (int q = 0; q < 4; q++) {
            ulonglong2 rv = row[q];
            S[2*q]   = ffma2p(mp, rv.x, S[2*q]);
            S[2*q+1] = ffma2p(mp, rv.y, S[2*q+1]);
        }
    }

    float2 acc = make_float2(0.0f, 0.0f);

    #pragma unroll
    for (int k = 0; k < 4; k++) {
        float2 s0 = unpack2(S[0]), s1 = unpack2(S[1]);
        float2 s2 = unpack2(S[2]), s3 = unpack2(S[3]);
        float2 s4 = unpack2(S[4]), s5 = unpack2(S[5]);
        float2 s6 = unpack2(S[6]), s7 = unpack2(S[7]);
        float2 p01 = cmul(s0, s1);
        float2 p23 = cmul(s2, s3);
        float2 p45 = cmul(s4, s5);
        float2 p67 = cmul(s6, s7);
        float2 p = cmul(cmul(p01, p23), cmul(p45, p67));
        if (k & 1) { acc.x -= p.x; acc.y -= p.y; }
        else       { acc.x += p.x; acc.y += p.y; }

        if (k < 3) {
            const int b = (k == 1) ? 1 : 0;
            g ^= (1u << b);
            const float s = ((g >> b) & 1u) ? -2.0f : 2.0f;
            const ull sp = pack2(s, s);
            if (b == 0) {
                #pragma unroll
                for (int i = 0; i < 8; i++) S[i] = ffma2p(sp, rr1[i], S[i]);
            } else {
                const ulonglong2* row = (const ulonglong2*)&sAR[w][2 * 8];
                #pragma unroll
                for (int q = 0; q < 4; q++) {
                    ulonglong2 rv = row[q];
                    S[2*q]   = ffma2p(sp, rv.x, S[2*q]);
                    S[2*q+1] = ffma2p(sp, rv.y, S[2*q+1]);
                }
            }
        }
    }

    // Warp reduce (complex)
    #pragma unroll
    for (int off = 16; off > 0; off >>= 1) {
        acc.x += __shfl_xor_sync(0xFFFFFFFFu, acc.x, off);
        acc.y += __shfl_xor_sync(0xFFFFFFFFu, acc.y, off);
    }

    if (lane == 0) {
        // perm = acc / 128 ; K = |perm|^2 = |acc|^2 / 16384
        float kv = (acc.x * acc.x + acc.y * acc.y) * (1.0f / 16384.0f);
        Kout[a * NSAMP + bcol] = kv;
        Kout[bcol * NSAMP + a] = kv;
    }
}

// ---------------------------------------------------------------------------
extern "C" void kernel_launch(void* const* d_in, const int* in_sizes, int n_in,
                              void* d_out, int out_size)
{
    const float* x = (const float*)d_in[0];   // (256, 64)
    const float* W = (const float*)d_in[1];   // (120, 64)
    const float* b = (const float*)d_in[2];   // (120,)
    float* out = (float*)d_out;               // [x_emb (30720) | K (65536)]

    emb_v_kernel<<<NSAMP, 128>>>(x, W, b, out);
    pair_kernel_tri<<<528 * 8, 256>>>(out + NSAMP * EMB);
}

// round 13
// speedup vs baseline: 1.0406x; 1.0406x over previous
#include <cuda_runtime.h>
#include <cstdint>

#define NSAMP 256
#define EMB   120
#define DIN   64
#define MODES 16
#define NPH   8

#define PIf 3.14159265358979323846f

typedef unsigned long long ull;

// Persistent scratch for V, stored TRANSPOSED: [n][c][m] (c=0..7, m=0..15)
__device__ float2 g_V[NSAMP * NPH * MODES];

__device__ __forceinline__ float2 cmul(float2 a, float2 b) {
    return make_float2(a.x * b.x - a.y * b.y, a.x * b.y + a.y * b.x);
}

// Packed dual-FMA on native 64-bit operands (FFMA2, one issue slot)
__device__ __forceinline__ ull ffma2p(ull a, ull b, ull c) {
    ull d;
    asm("fma.rn.f32x2 %0, %1, %2, %3;" : "=l"(d) : "l"(a), "l"(b), "l"(c));
    return d;
}
__device__ __forceinline__ ull pack2(float x, float y) {
    ull d; asm("mov.b64 %0, {%1, %2};" : "=l"(d) : "f"(x), "f"(y)); return d;
}
__device__ __forceinline__ float2 unpack2(ull a) {
    float2 f; asm("mov.b64 {%0, %1}, %2;" : "=f"(f.x), "=f"(f.y) : "l"(a)); return f;
}

// ---------------------------------------------------------------------------
// Kernel A: x_emb = sigmoid(x @ W^T + b); build V[n] (16x8 complex) per sample.
// V propagation over 64 threads (c-major lanes, odd-layer exchange via shfl).
// Also writes the K diagonal (=1.0).
// ---------------------------------------------------------------------------
__global__ void __launch_bounds__(128) emb_v_kernel(
    const float* __restrict__ x,
    const float* __restrict__ W,
    const float* __restrict__ b,
    float* __restrict__ out_emb,
    float* __restrict__ Kout)
{
    const int n = blockIdx.x;
    const int t = threadIdx.x;

    __shared__ float xs[DIN];
    __shared__ float semb[EMB];
    __shared__ float4 trig[60];

    if (t < DIN) xs[t] = x[n * DIN + t];
    if (t == 127) Kout[n * NSAMP + n] = 1.0f;   // diagonal of K
    __syncthreads();

    if (t < EMB) {
        float acc = b[t];
        const float* wr = W + t * DIN;
        #pragma unroll
        for (int j = 0; j < DIN; j++) acc += xs[j] * wr[j];
        float s = 1.0f / (1.0f + expf(-acc));
        semb[t] = s;
        out_emb[n * EMB + t] = s;
    }
    __syncthreads();

    if (t < 60) {
        float th = semb[2 * t]     * (0.5f * PIf);
        float ph = semb[2 * t + 1] * (2.0f * PIf);
        float st_, ct_, sp_, cp_;
        sincosf(th, &st_, &ct_);
        sincosf(ph, &sp_, &cp_);
        trig[t] = make_float4(ct_, st_, cp_, sp_);
    }
    __syncthreads();

    // 64 threads: tid = c*8 + p ; thread holds rows 2p, 2p+1 of column c.
    if (t < 64) {
        const int p = t & 7;
        const int lane = t & 31;
        float2 t0 = make_float2((2 * p     == (t >> 3)) ? 1.0f : 0.0f, 0.0f);
        float2 t1 = make_float2((2 * p + 1 == (t >> 3)) ? 1.0f : 0.0f, 0.0f);

        const int NBF[8] = {0, 8, 15, 23, 30, 38, 45, 53};

        #pragma unroll
        for (int d = 0; d < 8; d++) {
            if ((d & 1) == 0) {
                float4 tg = trig[NBF[d] + p];
                float2 epct = make_float2(tg.z * tg.x, tg.w * tg.x);
                float2 epst = make_float2(tg.z * tg.y, tg.w * tg.y);
                float2 n0 = cmul(epct, t0);
                n0.x -= tg.y * t1.x;  n0.y -= tg.y * t1.y;
                float2 n1 = cmul(epst, t0);
                n1.x += tg.x * t1.x;  n1.y += tg.x * t1.y;
                t0 = n0;  t1 = n1;
            } else {
                float2 vlow = t1;
                float2 vhigh;
                vhigh.x = __shfl_sync(0xFFFFFFFFu, t0.x, lane + 1, 32);
                vhigh.y = __shfl_sync(0xFFFFFFFFu, t0.y, lane + 1, 32);
                float2 nhigh = vhigh;
                if (p < 7) {
                    float4 tg = trig[NBF[d] + p];
                    float2 epct = make_float2(tg.z * tg.x, tg.w * tg.x);
                    float2 epst = make_float2(tg.z * tg.y, tg.w * tg.y);
                    float2 nlow = cmul(epct, vlow);
                    nlow.x -= tg.y * vhigh.x;  nlow.y -= tg.y * vhigh.y;
                    nhigh = cmul(epst, vlow);
                    nhigh.x += tg.x * vhigh.x; nhigh.y += tg.x * vhigh.y;
                    t1 = nlow;
                }
                float2 back;
                back.x = __shfl_sync(0xFFFFFFFFu, nhigh.x, lane - 1, 32);
                back.y = __shfl_sync(0xFFFFFFFFu, nhigh.y, lane - 1, 32);
                if (p > 0) t0 = back;
            }
        }

        const int c = t >> 3;
        g_V[n * (NPH * MODES) + c * MODES + 2 * p]     = t0;
        g_V[n * (NPH * MODES) + c * MODES + 2 * p + 1] = t1;
    }
}

// ---------------------------------------------------------------------------
// Kernel B (flat strict-upper-triangle, GLYNN): one warp per pair (a<b).
// W = blockIdx*8 + warp in [0, 32640); decode to (a,b). No block-wide sync:
// each warp owns its shared slices. perm via 128-term Gray-coded Glynn,
// lane t handles terms 4t..4t+3.
// ---------------------------------------------------------------------------
#define VROW 18   // padded row stride (float2 units)
#define NPAIR 32640

__global__ void __launch_bounds__(256, 4) pair_kernel_tri(float* __restrict__ Kout)
{
    const int tid  = threadIdx.x;
    const int w    = tid >> 5;
    const int lane = tid & 31;
    const int Wp   = blockIdx.x * 8 + w;   // pair index 0..32639

    // Decode strict upper triangle: largest b with b(b-1)/2 <= Wp, a = rem.
    int bq = (int)((1.0f + sqrtf(8.0f * (float)Wp + 1.0f)) * 0.5f);
    while (bq * (bq - 1) / 2 > Wp) bq--;
    while ((bq + 1) * bq / 2 <= Wp) bq++;
    const int bcol = bq;                       // 1..255
    const int a    = Wp - bq * (bq - 1) / 2;   // 0..bcol-1

    __shared__ alignas(16) float2 sVa[8][NPH * VROW];   // [w][i*18 + m]
    __shared__ alignas(16) float2 sVb[8][NPH * VROW];   // [w][j*18 + m]
    __shared__ alignas(16) ull    sAR[8][64];           // row-major: [w][i*8 + j]
    __shared__ alignas(16) ull    sRall[8][8];          // column sums over rows

    #pragma unroll
    for (int r = 0; r < 4; r++) {
        const int idx = lane + r * 32;
        const int row = idx >> 4, m = idx & 15;
        sVa[w][row * VROW + m] = g_V[a    * (NPH * MODES) + idx];
        sVb[w][row * VROW + m] = g_V[bcol * (NPH * MODES) + idx];
    }
    __syncwarp();

    // G[i][j] = sum_m conj(Va[m][i]) * Vb[m][j]; lane computes 2 entries.
    #pragma unroll
    for (int e = 0; e < 2; e++) {
        const int idx = lane + e * 32;
        const int i = idx >> 3, j = idx & 7;
        const float4* pa = (const float4*)&sVa[w][i * VROW];
        const float4* pb = (const float4*)&sVb[w][j * VROW];
        float2 acc = make_float2(0.0f, 0.0f);
        #pragma unroll
        for (int mm = 0; mm < 8; mm++) {
            float4 va2 = pa[mm];
            float4 vb2 = pb[mm];
            acc.x += va2.x * vb2.x + va2.y * vb2.y;
            acc.y += va2.x * vb2.y - va2.y * vb2.x;
            acc.x += va2.z * vb2.z + va2.w * vb2.w;
            acc.y += va2.z * vb2.w - va2.w * vb2.z;
        }
        sAR[w][idx] = pack2(acc.x, acc.y);   // row-major store: [i*8 + j]
    }
    __syncwarp();

    // Column sums over all rows: R_all[j] = sum_i G[i][j]  (lanes 0..7)
    if (lane < 8) {
        float2 s = make_float2(0.0f, 0.0f);
        #pragma unroll
        for (int i = 0; i < 8; i++) {
            float2 v = unpack2(sAR[w][i * 8 + lane]);
            s.x += v.x; s.y += v.y;
        }
        sRall[w][lane] = pack2(s.x, s.y);
    }
    __syncwarp();

    // Register-cache row 1 (delta bit 0: flips at k=1 and k=3).
    ull rr1[8];
    {
        const ulonglong2* r1 = (const ulonglong2*)&sAR[w][8];
        #pragma unroll
        for (int q = 0; q < 4; q++) {
            ulonglong2 v = r1[q];
            rr1[2*q] = v.x; rr1[2*q+1] = v.y;
        }
    }

    // Gray state: g = gray(4*lane) over 7 bits (bit b <-> row b+1); bit0 = 0.
    unsigned g = ((4u * lane) ^ (2u * lane)) & 0x7Fu;

    // Init S = R_all - 2 * sum_{set bits b=1..6} row_{b+1}
    ull S[8];
    {
        const ulonglong2* ra = (const ulonglong2*)&sRall[w][0];
        #pragma unroll
        for (int q = 0; q < 4; q++) {
            ulonglong2 v = ra[q];
            S[2*q] = v.x; S[2*q+1] = v.y;
        }
    }
    #pragma unroll
    for (int b = 1; b < 7; b++) {
        const float msk = -2.0f * (float)((g >> b) & 1u);
        const ull mp = pack2(msk, msk);
        const ulonglong2* row = (const ulonglong2*)&sAR[w][(b + 1) * 8];
        #pragma unroll
        for (int q = 0; q < 4; q++) {
            ulonglong2 rv = row[q];
            S[2*q]   = ffma2p(mp, rv.x, S[2*q]);
            S[2*q+1] = ffma2p(mp, rv.y, S[2*q+1]);
        }
    }

    float2 acc = make_float2(0.0f, 0.0f);

    #pragma unroll
    for (int k = 0; k < 4; k++) {
        float2 s0 = unpack2(S[0]), s1 = unpack2(S[1]);
        float2 s2 = unpack2(S[2]), s3 = unpack2(S[3]);
        float2 s4 = unpack2(S[4]), s5 = unpack2(S[5]);
        float2 s6 = unpack2(S[6]), s7 = unpack2(S[7]);
        float2 p01 = cmul(s0, s1);
        float2 p23 = cmul(s2, s3);
        float2 p45 = cmul(s4, s5);
        float2 p67 = cmul(s6, s7);
        float2 p = cmul(cmul(p01, p23), cmul(p45, p67));
        if (k & 1) { acc.x -= p.x; acc.y -= p.y; }
        else       { acc.x += p.x; acc.y += p.y; }

        if (k < 3) {
            const int b = (k == 1) ? 1 : 0;
            g ^= (1u << b);
            const float s = ((g >> b) & 1u) ? -2.0f : 2.0f;
            const ull sp = pack2(s, s);
            if (b == 0) {
                #pragma unroll
                for (int i = 0; i < 8; i++) S[i] = ffma2p(sp, rr1[i], S[i]);
            } else {
                const ulonglong2* row = (const ulonglong2*)&sAR[w][2 * 8];
                #pragma unroll
                for (int q = 0; q < 4; q++) {
                    ulonglong2 rv = row[q];
                    S[2*q]   = ffma2p(sp, rv.x, S[2*q]);
                    S[2*q+1] = ffma2p(sp, rv.y, S[2*q+1]);
                }
            }
        }
    }

    // Warp reduce (complex)
    #pragma unroll
    for (int off = 16; off > 0; off >>= 1) {
        acc.x += __shfl_xor_sync(0xFFFFFFFFu, acc.x, off);
        acc.y += __shfl_xor_sync(0xFFFFFFFFu, acc.y, off);
    }

    if (lane == 0) {
        // perm = acc / 128 ; K = |perm|^2 = |acc|^2 / 16384
        float kv = (acc.x * acc.x + acc.y * acc.y) * (1.0f / 16384.0f);
        Kout[a * NSAMP + bcol] = kv;
        Kout[bcol * NSAMP + a] = kv;
    }
}

// ---------------------------------------------------------------------------
extern "C" void kernel_launch(void* const* d_in, const int* in_sizes, int n_in,
                              void* d_out, int out_size)
{
    const float* x = (const float*)d_in[0];   // (256, 64)
    const float* W = (const float*)d_in[1];   // (120, 64)
    const float* b = (const float*)d_in[2];   // (120,)
    float* out = (float*)d_out;               // [x_emb (30720) | K (65536)]

    emb_v_kernel<<<NSAMP, 128>>>(x, W, b, out, out + NSAMP * EMB);
    pair_kernel_tri<<<NPAIR / 8, 256>>>(out + NSAMP * EMB);
}

// round 14
// speedup vs baseline: 1.0414x; 1.0008x over previous
#include <cuda_runtime.h>
#include <cstdint>
#include <cstring>

#define NSAMP 256
#define EMB   120
#define DIN   64
#define MODES 16
#define NPH   8

#define PIf 3.14159265358979323846f

typedef unsigned long long ull;

// Persistent scratch for V, stored TRANSPOSED: [n][c][m] (c=0..7, m=0..15)
__device__ float2 g_V[NSAMP * NPH * MODES];

__device__ __forceinline__ float2 cmul(float2 a, float2 b) {
    return make_float2(a.x * b.x - a.y * b.y, a.x * b.y + a.y * b.x);
}

// Packed dual-FMA on native 64-bit operands (FFMA2, one issue slot)
__device__ __forceinline__ ull ffma2p(ull a, ull b, ull c) {
    ull d;
    asm("fma.rn.f32x2 %0, %1, %2, %3;" : "=l"(d) : "l"(a), "l"(b), "l"(c));
    return d;
}
// C-level pack/unpack: let ptxas alias the register pair (no asm barrier)
union pk { ull u; float2 f; };
__device__ __forceinline__ ull pack2(float x, float y) {
    pk v; v.f = make_float2(x, y); return v.u;
}
__device__ __forceinline__ float2 unpack2(ull a) {
    pk v; v.u = a; return v.f;
}

// ---------------------------------------------------------------------------
// Kernel A: x_emb = sigmoid(x @ W^T + b); build V[n] (16x8 complex) per sample.
// V propagation over 64 threads (c-major lanes, odd-layer exchange via shfl).
// Also writes the K diagonal (=1.0).
// ---------------------------------------------------------------------------
__global__ void __launch_bounds__(128) emb_v_kernel(
    const float* __restrict__ x,
    const float* __restrict__ W,
    const float* __restrict__ b,
    float* __restrict__ out_emb,
    float* __restrict__ Kout)
{
    const int n = blockIdx.x;
    const int t = threadIdx.x;

    __shared__ float xs[DIN];
    __shared__ float semb[EMB];
    __shared__ float4 trig[60];

    if (t < DIN) xs[t] = x[n * DIN + t];
    if (t == 127) Kout[n * NSAMP + n] = 1.0f;   // diagonal of K
    __syncthreads();

    if (t < EMB) {
        float acc = b[t];
        const float* wr = W + t * DIN;
        #pragma unroll
        for (int j = 0; j < DIN; j++) acc += xs[j] * wr[j];
        float s = 1.0f / (1.0f + expf(-acc));
        semb[t] = s;
        out_emb[n * EMB + t] = s;
    }
    __syncthreads();

    if (t < 60) {
        float th = semb[2 * t]     * (0.5f * PIf);
        float ph = semb[2 * t + 1] * (2.0f * PIf);
        float st_, ct_, sp_, cp_;
        sincosf(th, &st_, &ct_);
        sincosf(ph, &sp_, &cp_);
        trig[t] = make_float4(ct_, st_, cp_, sp_);
    }
    __syncthreads();

    // 64 threads: tid = c*8 + p ; thread holds rows 2p, 2p+1 of column c.
    if (t < 64) {
        const int p = t & 7;
        const int lane = t & 31;
        float2 t0 = make_float2((2 * p     == (t >> 3)) ? 1.0f : 0.0f, 0.0f);
        float2 t1 = make_float2((2 * p + 1 == (t >> 3)) ? 1.0f : 0.0f, 0.0f);

        const int NBF[8] = {0, 8, 15, 23, 30, 38, 45, 53};

        #pragma unroll
        for (int d = 0; d < 8; d++) {
            if ((d & 1) == 0) {
                float4 tg = trig[NBF[d] + p];
                float2 epct = make_float2(tg.z * tg.x, tg.w * tg.x);
                float2 epst = make_float2(tg.z * tg.y, tg.w * tg.y);
                float2 n0 = cmul(epct, t0);
                n0.x -= tg.y * t1.x;  n0.y -= tg.y * t1.y;
                float2 n1 = cmul(epst, t0);
                n1.x += tg.x * t1.x;  n1.y += tg.x * t1.y;
                t0 = n0;  t1 = n1;
            } else {
                float2 vlow = t1;
                float2 vhigh;
                vhigh.x = __shfl_sync(0xFFFFFFFFu, t0.x, lane + 1, 32);
                vhigh.y = __shfl_sync(0xFFFFFFFFu, t0.y, lane + 1, 32);
                float2 nhigh = vhigh;
                if (p < 7) {
                    float4 tg = trig[NBF[d] + p];
                    float2 epct = make_float2(tg.z * tg.x, tg.w * tg.x);
                    float2 epst = make_float2(tg.z * tg.y, tg.w * tg.y);
                    float2 nlow = cmul(epct, vlow);
                    nlow.x -= tg.y * vhigh.x;  nlow.y -= tg.y * vhigh.y;
                    nhigh = cmul(epst, vlow);
                    nhigh.x += tg.x * vhigh.x; nhigh.y += tg.x * vhigh.y;
                    t1 = nlow;
                }
                float2 back;
                back.x = __shfl_sync(0xFFFFFFFFu, nhigh.x, lane - 1, 32);
                back.y = __shfl_sync(0xFFFFFFFFu, nhigh.y, lane - 1, 32);
                if (p > 0) t0 = back;
            }
        }

        const int c = t >> 3;
        g_V[n * (NPH * MODES) + c * MODES + 2 * p]     = t0;
        g_V[n * (NPH * MODES) + c * MODES + 2 * p + 1] = t1;
    }
}

// ---------------------------------------------------------------------------
// Kernel B (flat strict-upper-triangle, GLYNN): one warp per pair (a<b).
// W = blockIdx*8 + warp in [0, 32640); decode to (a,b). No block-wide sync.
// G phase: lane computes entries (i, j0) and (i, j0+1) sharing the Va column
// (8 float4 loads amortized over both) and stores them with one STS.128.
// perm via 128-term Gray-coded Glynn, lane t handles terms 4t..4t+3.
// ---------------------------------------------------------------------------
#define VROW 18   // padded row stride (float2 units)
#define NPAIR 32640

__global__ void __launch_bounds__(256, 4) pair_kernel_tri(float* __restrict__ Kout)
{
    const int tid  = threadIdx.x;
    const int w    = tid >> 5;
    const int lane = tid & 31;
    const int Wp   = blockIdx.x * 8 + w;   // pair index 0..32639

    // Decode strict upper triangle: largest b with b(b-1)/2 <= Wp, a = rem.
    int bq = (int)((1.0f + sqrtf(8.0f * (float)Wp + 1.0f)) * 0.5f);
    while (bq * (bq - 1) / 2 > Wp) bq--;
    while ((bq + 1) * bq / 2 <= Wp) bq++;
    const int bcol = bq;                       // 1..255
    const int a    = Wp - bq * (bq - 1) / 2;   // 0..bcol-1

    __shared__ alignas(16) float2 sVa[8][NPH * VROW];   // [w][i*18 + m]
    __shared__ alignas(16) float2 sVb[8][NPH * VROW];   // [w][j*18 + m]
    __shared__ alignas(16) ull    sAR[8][64];           // row-major: [w][i*8 + j]
    __shared__ alignas(16) ull    sRall[8][8];          // column sums over rows

    #pragma unroll
    for (int r = 0; r < 4; r++) {
        const int idx = lane + r * 32;
        const int row = idx >> 4, m = idx & 15;
        sVa[w][row * VROW + m] = g_V[a    * (NPH * MODES) + idx];
        sVb[w][row * VROW + m] = g_V[bcol * (NPH * MODES) + idx];
    }
    __syncwarp();

    // G[i][j] = sum_m conj(Va[m][i]) * Vb[m][j]
    // Lane: i = lane>>2, j0 = (lane&3)*2, j1 = j0+1.
    {
        const int i  = lane >> 2;
        const int j0 = (lane & 3) * 2;
        const float4* pa  = (const float4*)&sVa[w][i * VROW];
        const float4* pb0 = (const float4*)&sVb[w][j0 * VROW];
        const float4* pb1 = (const float4*)&sVb[w][(j0 + 1) * VROW];
        float2 a0 = make_float2(0.0f, 0.0f);
        float2 a1 = make_float2(0.0f, 0.0f);
        #pragma unroll
        for (int mm = 0; mm < 8; mm++) {
            float4 va2 = pa[mm];
            float4 vb0 = pb0[mm];
            float4 vb1 = pb1[mm];
            a0.x += va2.x * vb0.x + va2.y * vb0.y;
            a0.y += va2.x * vb0.y - va2.y * vb0.x;
            a0.x += va2.z * vb0.z + va2.w * vb0.w;
            a0.y += va2.z * vb0.w - va2.w * vb0.z;
            a1.x += va2.x * vb1.x + va2.y * vb1.y;
            a1.y += va2.x * vb1.y - va2.y * vb1.x;
            a1.x += va2.z * vb1.z + va2.w * vb1.w;
            a1.y += va2.z * vb1.w - va2.w * vb1.z;
        }
        ulonglong2 st2;
        st2.x = pack2(a0.x, a0.y);
        st2.y = pack2(a1.x, a1.y);
        *(ulonglong2*)&sAR[w][i * 8 + j0] = st2;   // one STS.128
    }
    __syncwarp();

    // Column sums over all rows: R_all[j] = sum_i G[i][j]  (lanes 0..7)
    if (lane < 8) {
        float2 s = make_float2(0.0f, 0.0f);
        #pragma unroll
        for (int i = 0; i < 8; i++) {
            float2 v = unpack2(sAR[w][i * 8 + lane]);
            s.x += v.x; s.y += v.y;
        }
        sRall[w][lane] = pack2(s.x, s.y);
    }
    __syncwarp();

    // Register-cache row 1 (delta bit 0: flips at k=1 and k=3).
    ull rr1[8];
    {
        const ulonglong2* r1 = (const ulonglong2*)&sAR[w][8];
        #pragma unroll
        for (int q = 0; q < 4; q++) {
            ulonglong2 v = r1[q];
            rr1[2*q] = v.x; rr1[2*q+1] = v.y;
        }
    }

    // Gray state: g = gray(4*lane) over 7 bits (bit b <-> row b+1); bit0 = 0.
    unsigned g = ((4u * lane) ^ (2u * lane)) & 0x7Fu;

    // Init S = R_all - 2 * sum_{set bits b=1..6} row_{b+1}
    ull S[8];
    {
        const ulonglong2* ra = (const ulonglong2*)&sRall[w][0];
        #pragma unroll
        for (int q = 0; q < 4; q++) {
            ulonglong2 v = ra[q];
            S[2*q] = v.x; S[2*q+1] = v.y;
        }
    }
    #pragma unroll
    for (int b = 1; b < 7; b++) {
        const float msk = -2.0f * (float)((g >> b) & 1u);
        const ull mp = pack2(msk, msk);
        const ulonglong2* row = (const ulonglong2*)&sAR[w][(b + 1) * 8];
        #pragma unroll
        for (int q = 0; q < 4; q++) {
            ulonglong2 rv = row[q];
            S[2*q]   = ffma2p(mp, rv.x, S[2*q]);
            S[2*q+1] = ffma2p(mp, rv.y, S[2*q+1]);
        }
    }

    float2 acc = make_float2(0.0f, 0.0f);

    #pragma unroll
    for (int k = 0; k < 4; k++) {
        float2 s0 = unpack2(S[0]), s1 = unpack2(S[1]);
        float2 s2 = unpack2(S[2]), s3 = unpack2(S[3]);
        float2 s4 = unpack2(S[4]), s5 = unpack2(S[5]);
        float2 s6 = unpack2(S[6]), s7 = unpack2(S[7]);
        float2 p01 = cmul(s0, s1);
        float2 p23 = cmul(s2, s3);
        float2 p45 = cmul(s4, s5);
        float2 p67 = cmul(s6, s7);
        float2 p = cmul(cmul(p01, p23), cmul(p45, p67));
        if (k & 1) { acc.x -= p.x; acc.y -= p.y; }
        else       { acc.x += p.x; acc.y += p.y; }

        if (k < 3) {
            const int b = (k == 1) ? 1 : 0;
            g ^= (1u << b);
            const float s = ((g >> b) & 1u) ? -2.0f : 2.0f;
            const ull sp = pack2(s, s);
            if (b == 0) {
                #pragma unroll
                for (int i = 0; i < 8; i++) S[i] = ffma2p(sp, rr1[i], S[i]);
            } else {
                const ulonglong2* row = (const ulonglong2*)&sAR[w][2 * 8];
                #pragma unroll
                for (int q = 0; q < 4; q++) {
                    ulonglong2 rv = row[q];
                    S[2*q]   = ffma2p(sp, rv.x, S[2*q]);
                    S[2*q+1] = ffma2p(sp, rv.y, S[2*q+1]);
                }
            }
        }
    }

    // Warp reduce (complex)
    #pragma unroll
    for (int off = 16; off > 0; off >>= 1) {
        acc.x += __shfl_xor_sync(0xFFFFFFFFu, acc.x, off);
        acc.y += __shfl_xor_sync(0xFFFFFFFFu, acc.y, off);
    }

    if (lane == 0) {
        // perm = acc / 128 ; K = |perm|^2 = |acc|^2 / 16384
        float kv = (acc.x * acc.x + acc.y * acc.y) * (1.0f / 16384.0f);
        Kout[a * NSAMP + bcol] = kv;
        Kout[bcol * NSAMP + a] = kv;
    }
}

// ---------------------------------------------------------------------------
extern "C" void kernel_launch(void* const* d_in, const int* in_sizes, int n_in,
                              void* d_out, int out_size)
{
    const float* x = (const float*)d_in[0];   // (256, 64)
    const float* W = (const float*)d_in[1];   // (120, 64)
    const float* b = (const float*)d_in[2];   // (120,)
    float* out = (float*)d_out;               // [x_emb (30720) | K (65536)]

    emb_v_kernel<<<NSAMP, 128>>>(x, W, b, out, out + NSAMP * EMB);
    pair_kernel_tri<<<NPAIR / 8, 256>>>(out + NSAMP * EMB);
}